// round 1
// baseline (speedup 1.0000x reference)
#include <cuda_runtime.h>

// Problem constants
#define NT    48
#define NE    48
#define BATCH 32
#define VS    512
#define M_ROWS (NT * BATCH)   // 1536 rows for both GEMMs

// Scratch for the two GEMM outputs (3 MB each) — device globals (no alloc)
__device__ float g_A[M_ROWS * VS];   // ta + b1, layout [t*32+b][h]
__device__ float g_E[M_ROWS * VS];   // eb,       layout [n*32+b][h]

// ---------------------------------------------------------------------------
// Stage 1: C[m,h] = sum_v X[m,v] * W1[h, off+v]   (+ b1[h] for z==0)
// blockIdx.z: 0 -> targets into g_A (with bias), 1 -> embeddings into g_E
// Tiles: BM=64, BN=64, BK=16, 256 threads, 4x4 per-thread micro-tile.
// ---------------------------------------------------------------------------
#define BM 64
#define BN 64
#define BK 16

__global__ __launch_bounds__(256) void gemm_kernel(
    const float* __restrict__ Tg, const float* __restrict__ Eg,
    const float* __restrict__ W1, const float* __restrict__ b1)
{
    const int z = blockIdx.z;
    const float* __restrict__ X = z ? Eg : Tg;
    float* __restrict__ C = z ? g_E : g_A;
    const int w_off = z ? VS : 0;

    __shared__ float Xs[BK][BM + 4];
    __shared__ float Ws[BK][BN + 4];

    const int tid = threadIdx.x;
    const int m0 = blockIdx.y * BM;
    const int h0 = blockIdx.x * BN;

    const int tx = tid & 15;          // output col group (4 cols)
    const int ty = tid >> 4;          // output row group (4 rows)

    // global->shared load mapping: one float4 per array per thread
    const int lr = tid >> 2;          // 0..63 tile row
    const int lc = (tid & 3) * 4;     // 0,4,8,12 k offset

    float acc[4][4];
#pragma unroll
    for (int i = 0; i < 4; i++)
#pragma unroll
        for (int j = 0; j < 4; j++) acc[i][j] = 0.f;

    const float* xg = X  + (size_t)(m0 + lr) * VS + lc;
    const float* wg = W1 + (size_t)(h0 + lr) * (2 * VS) + w_off + lc;

    for (int k0 = 0; k0 < VS; k0 += BK) {
        float4 xa = *(const float4*)(xg + k0);
        float4 wa = *(const float4*)(wg + k0);

        __syncthreads();   // previous iteration's compute done before overwrite
        Xs[lc + 0][lr] = xa.x; Xs[lc + 1][lr] = xa.y;
        Xs[lc + 2][lr] = xa.z; Xs[lc + 3][lr] = xa.w;
        Ws[lc + 0][lr] = wa.x; Ws[lc + 1][lr] = wa.y;
        Ws[lc + 2][lr] = wa.z; Ws[lc + 3][lr] = wa.w;
        __syncthreads();

#pragma unroll
        for (int k = 0; k < BK; k++) {
            float a[4], b[4];
            *(float4*)a = *(const float4*)&Xs[k][ty * 4];
            *(float4*)b = *(const float4*)&Ws[k][tx * 4];
#pragma unroll
            for (int i = 0; i < 4; i++)
#pragma unroll
                for (int j = 0; j < 4; j++)
                    acc[i][j] = fmaf(a[i], b[j], acc[i][j]);
        }
    }

    // epilogue: optional bias along h, vectorized store
    const int hbase = h0 + tx * 4;
    float4 bias = make_float4(0.f, 0.f, 0.f, 0.f);
    if (z == 0) bias = *(const float4*)(b1 + hbase);

#pragma unroll
    for (int i = 0; i < 4; i++) {
        const int m = m0 + ty * 4 + i;
        float4 v;
        v.x = acc[i][0] + bias.x;
        v.y = acc[i][1] + bias.y;
        v.z = acc[i][2] + bias.z;
        v.w = acc[i][3] + bias.w;
        *(float4*)(C + (size_t)m * VS + hbase) = v;
    }
}

// ---------------------------------------------------------------------------
// Stage 2: out[t,n,b] = sum_h w2[h]*tanh(A[t,b,h] + E[n,b,h]) + b2
// One block per (t,b); 8 warps; warp w covers n = w, w+8, ...
// Lane-parallel over h with float4 loads; warp shuffle reduction.
// ---------------------------------------------------------------------------
__device__ __forceinline__ float tanh_fast(float x) {
    float y;
    asm("tanh.approx.f32 %0, %1;" : "=f"(y) : "f"(x));
    return y;
}

__global__ __launch_bounds__(256) void fuse_kernel(
    const float* __restrict__ W2, const float* __restrict__ b2,
    float* __restrict__ out)
{
    __shared__ float4 sA[VS / 4];   // A row for this (t,b)
    __shared__ float4 sW[VS / 4];   // w2

    const int bid = blockIdx.x;          // t*32 + b
    const int t  = bid >> 5;
    const int bb = bid & 31;
    const int tid = threadIdx.x;

    const float4* A4 = (const float4*)(g_A + (size_t)bid * VS);
    const float4* W4 = (const float4*)W2;
    if (tid < 128) sA[tid] = A4[tid];
    else           sW[tid - 128] = W4[tid - 128];
    __syncthreads();

    const int warp = tid >> 5;
    const int lane = tid & 31;
    const float b2v = __ldg(b2);

    for (int n = warp; n < NE; n += 8) {
        const float4* E4 = (const float4*)(g_E + (size_t)(n * BATCH + bb) * VS);
        float acc = 0.f;
#pragma unroll
        for (int j = 0; j < 4; j++) {
            const int idx = lane + (j << 5);
            float4 e = E4[idx];
            float4 a = sA[idx];
            float4 w = sW[idx];
            acc = fmaf(w.x, tanh_fast(a.x + e.x), acc);
            acc = fmaf(w.y, tanh_fast(a.y + e.y), acc);
            acc = fmaf(w.z, tanh_fast(a.z + e.z), acc);
            acc = fmaf(w.w, tanh_fast(a.w + e.w), acc);
        }
#pragma unroll
        for (int off = 16; off; off >>= 1)
            acc += __shfl_xor_sync(0xffffffffu, acc, off);
        if (lane == 0)
            out[((size_t)t * NE + n) * BATCH + bb] = acc + b2v;
    }
}

// ---------------------------------------------------------------------------
// Launch: inputs in metadata order: targets, embeddings, W1, b1, W2, b2
// ---------------------------------------------------------------------------
extern "C" void kernel_launch(void* const* d_in, const int* in_sizes, int n_in,
                              void* d_out, int out_size)
{
    const float* targets    = (const float*)d_in[0];
    const float* embeddings = (const float*)d_in[1];
    const float* W1         = (const float*)d_in[2];
    const float* b1         = (const float*)d_in[3];
    const float* W2         = (const float*)d_in[4];
    const float* b2         = (const float*)d_in[5];
    float* out = (float*)d_out;

    dim3 g1(VS / BN, M_ROWS / BM, 2);   // 8 x 24 x 2 = 384 blocks
    gemm_kernel<<<g1, 256>>>(targets, embeddings, W1, b1);
    fuse_kernel<<<NT * BATCH, 256>>>(W2, b2, out);
}